// round 14
// baseline (speedup 1.0000x reference)
#include <cuda_runtime.h>
#include <cuda_fp16.h>
#include <cstdint>

#define BB   128
#define SSEQ 513
#define HH   256
#define SSH  (SSEQ * HH)

// ---------------- smem layout ----------------
// X resident: 128 rows x 256 fp16, 528B row stride (conflict-free ldmatrix)
#define XROWB 528
#define XSMB  (128 * XROWB)          // 67584
// W ring: k=64 fp16 tiles, 128 rows x 144B, 2 slots
#define KT    64
#define ROWB  144
#define TILEB (128 * ROWB)           // 18432
#define OBS   (XSMB + 2 * TILEB)     // bias sums (256 floats)
#define SMTOT (OBS + 1024)           // 105472
#define NUNIT 8                      // 2 n-halves x 4 k-tiles

__device__ __forceinline__ uint32_t smem_u32(const void* p) {
    uint32_t a;
    asm("{ .reg .u64 t; cvta.to.shared.u64 t, %1; cvt.u32.u64 %0, t; }" : "=r"(a) : "l"(p));
    return a;
}
__device__ __forceinline__ void ldsm_x4(uint32_t* r, uint32_t addr) {
    asm volatile("ldmatrix.sync.aligned.m8n8.x4.shared.b16 {%0,%1,%2,%3}, [%4];"
                 : "=r"(r[0]), "=r"(r[1]), "=r"(r[2]), "=r"(r[3]) : "r"(addr));
}
__device__ __forceinline__ void mma_f16(float* d, const uint32_t* a, uint32_t b0, uint32_t b1) {
    asm volatile(
        "mma.sync.aligned.m16n8k16.row.col.f32.f16.f16.f32 "
        "{%0,%1,%2,%3}, {%4,%5,%6,%7}, {%8,%9}, {%0,%1,%2,%3};"
        : "+f"(d[0]), "+f"(d[1]), "+f"(d[2]), "+f"(d[3])
        : "r"(a[0]), "r"(a[1]), "r"(a[2]), "r"(a[3]), "r"(b0), "r"(b1));
}
__device__ __forceinline__ uint2 f4_to_h4(float4 v) {
    __half2 h0 = __floats2half2_rn(v.x, v.y);
    __half2 h1 = __floats2half2_rn(v.z, v.w);
    uint2 u;
    u.x = *reinterpret_cast<uint32_t*>(&h0);
    u.y = *reinterpret_cast<uint32_t*>(&h1);
    return u;
}

// ---- single fused kernel: ONE CTA per s, full N=256, X converted once,
//      W converted per-unit from fp32 (L2-resident) ----
// out[0:128, s, 0:256] = x[:,s,:] @ W[idx]^T + sum_l bias[l]
__global__ __launch_bounds__(256, 2)
void pmha_fused1_kernel(const float* __restrict__ x,
                        const float* __restrict__ W,
                        const float* __restrict__ bias,
                        float* __restrict__ out)
{
    extern __shared__ char smem[];
    const uint32_t sb = smem_u32(smem);
    const uint32_t wbase = sb + XSMB;
    const int tid  = threadIdx.x;
    const int lane = tid & 31;
    const int wid  = tid >> 5;
    const int tg   = lane >> 2;
    const int tig  = lane & 3;
    const int wm   = (wid >> 2) * 64;
    const int wn   = (wid & 3) * 32;
    const int s    = blockIdx.x;
    const int widx = (s < 3) ? s : ((s & 1) ? 3 : 4);

    const float* xsrc = x + (size_t)s * HH;
    const float* Wf   = W + (size_t)widx * (HH * HH);

    // ---- W staging (fp32 LDG -> cvt -> fp16 STS), unit u into ring slot u&1 ----
    // 128 rows x 64 floats per tile; 2 threads per row, 32 floats (8 float4) each
    const int srow = tid >> 1;
    const int shalf = tid & 1;
    auto stageW = [&](int u) {
        const int nh = u >> 2;
        const int k0 = (u & 3) * KT;
        const float* wr = Wf + (size_t)(nh * 128 + srow) * HH + k0 + shalf * 32;
        char* dst = smem + XSMB + (u & 1) * TILEB + (uint32_t)srow * ROWB + shalf * 64;
        #pragma unroll
        for (int bat = 0; bat < 2; ++bat) {
            float4 v[4];
            #pragma unroll
            for (int i = 0; i < 4; ++i)
                v[i] = *reinterpret_cast<const float4*>(wr + bat * 16 + i * 4);
            #pragma unroll
            for (int i = 0; i < 4; ++i)
                *reinterpret_cast<uint2*>(dst + bat * 32 + i * 8) = f4_to_h4(v[i]);
        }
    };

    // ---- prologue: bias presum + X conversion + stage W unit 0 ----
    {
        float v = 0.0f;
        #pragma unroll
        for (int l = 0; l < 5; ++l) v += bias[l * HH + tid];
        *reinterpret_cast<float*>(smem + OBS + tid * 4) = v;
    }
    stageW(0);
    {
        const int crow = tid >> 6;          // 0..3
        const int cc4  = tid & 63;          // float4 col 0..63
        #pragma unroll 8
        for (int p = 0; p < 32; ++p) {
            const int row = p * 4 + crow;
            float4 v = *reinterpret_cast<const float4*>(xsrc + (size_t)row * SSH + cc4 * 4);
            *reinterpret_cast<uint2*>(smem + (uint32_t)row * XROWB + (uint32_t)cc4 * 8) = f4_to_h4(v);
        }
    }

    // ldmatrix base addresses
    const int lr = lane & 15;
    const int lc = lane >> 4;
    uint32_t aA[4], aB[2];
    #pragma unroll
    for (int i = 0; i < 4; ++i)
        aA[i] = sb + (uint32_t)(wm + i * 16 + lr) * XROWB + lc * 16;
    #pragma unroll
    for (int jj = 0; jj < 2; ++jj)
        aB[jj] = wbase + (uint32_t)(wn + jj * 16 + lr) * ROWB + lc * 16;

    float acc[4][4][4] = {};

    const float* bs = reinterpret_cast<const float*>(smem + OBS);
    auto epilogue = [&](int n0) {
        float bA[4], bB[4];
        #pragma unroll
        for (int j = 0; j < 4; ++j) {
            const int c = wn + j * 8 + 2 * tig;
            bA[j] = bs[n0 + c];
            bB[j] = bs[n0 + c + 1];
        }
        #pragma unroll
        for (int i = 0; i < 4; ++i) {
            const int r0 = wm + i * 16 + tg;
            float* o0 = out + (size_t)r0 * SSH + (size_t)s * HH + n0;
            float* o1 = o0 + (size_t)8 * SSH;
            #pragma unroll
            for (int j = 0; j < 4; ++j) {
                const int c = wn + j * 8 + 2 * tig;
                float2 v0 = make_float2(acc[i][j][0] + bA[j], acc[i][j][1] + bB[j]);
                float2 v1 = make_float2(acc[i][j][2] + bA[j], acc[i][j][3] + bB[j]);
                *reinterpret_cast<float2*>(o0 + c) = v0;
                *reinterpret_cast<float2*>(o1 + c) = v1;
            }
        }
    };

    #pragma unroll
    for (int u = 0; u < NUNIT; ++u) {
        __syncthreads();    // publishes stage of slot u (prev iter / prologue); retires readers of slot (u+1)&1

        if (u + 1 < NUNIT) stageW(u + 1);   // write other slot; overlaps compute below

        const uint32_t wst = (u & 1) * TILEB;
        const uint32_t xkt = (uint32_t)(u & 3) * 128;   // 64 fp16 = 128B per k-tile
        #pragma unroll
        for (int ks = 0; ks < 4; ++ks) {
            uint32_t a[4][4], b[2][4];
            #pragma unroll
            for (int i = 0; i < 4; ++i) ldsm_x4(a[i], aA[i] + xkt + ks * 32);
            #pragma unroll
            for (int jj = 0; jj < 2; ++jj) ldsm_x4(b[jj], aB[jj] + wst + ks * 32);
            #pragma unroll
            for (int i = 0; i < 4; ++i)
                #pragma unroll
                for (int j = 0; j < 4; ++j) {
                    const int jj = j >> 1, sel = j & 1;
                    mma_f16(acc[i][j], a[i], b[jj][sel], b[jj][sel + 2]);
                }
        }

        if (u == 3) {       // n-half 0 complete: write it, reset acc
            epilogue(0);
            #pragma unroll
            for (int i = 0; i < 4; ++i)
                #pragma unroll
                for (int j = 0; j < 4; ++j)
                    #pragma unroll
                    for (int q = 0; q < 4; ++q) acc[i][j][q] = 0.0f;
        }
    }
    epilogue(128);
}

extern "C" void kernel_launch(void* const* d_in, const int* in_sizes, int n_in,
                              void* d_out, int out_size)
{
    const float* x    = (const float*)d_in[0];   // [128, 513, 256]
    const float* W    = (const float*)d_in[1];   // [5, 256, 256]
    const float* bias = (const float*)d_in[2];   // [5, 256]
    float* out        = (float*)d_out;           // [128, 513, 4, 64]

    cudaFuncSetAttribute(pmha_fused1_kernel, cudaFuncAttributeMaxDynamicSharedMemorySize, SMTOT);
    pmha_fused1_kernel<<<SSEQ, 256, SMTOT>>>(x, W, bias, out);
}

// round 15
// speedup vs baseline: 1.3520x; 1.3520x over previous
#include <cuda_runtime.h>
#include <cuda_fp16.h>
#include <cstdint>

#define BB   128
#define SSEQ 513
#define HH   256
#define SSH  (SSEQ * HH)

// ---------------- smem layout ----------------
#define XROWB 528                    // X resident: 128 x 256 fp16, 528B stride
#define XSMB  (128 * XROWB)          // 67584
#define WROWB 80                     // W ring rows: 32 fp16 = 64B + 16B pad
#define WTILEB (128 * WROWB)         // 10240
#define OBS   (XSMB + 2 * WTILEB)    // 88064
#define SMTOT (OBS + 1024)           // 89088
#define NUNIT 16                     // 2 n-halves x 8 k32-tiles

__device__ __forceinline__ uint32_t smem_u32(const void* p) {
    uint32_t a;
    asm("{ .reg .u64 t; cvta.to.shared.u64 t, %1; cvt.u32.u64 %0, t; }" : "=r"(a) : "l"(p));
    return a;
}
__device__ __forceinline__ void ldsm_x4(uint32_t* r, uint32_t addr) {
    asm volatile("ldmatrix.sync.aligned.m8n8.x4.shared.b16 {%0,%1,%2,%3}, [%4];"
                 : "=r"(r[0]), "=r"(r[1]), "=r"(r[2]), "=r"(r[3]) : "r"(addr));
}
__device__ __forceinline__ void mma_f16(float* d, const uint32_t* a, uint32_t b0, uint32_t b1) {
    asm volatile(
        "mma.sync.aligned.m16n8k16.row.col.f32.f16.f16.f32 "
        "{%0,%1,%2,%3}, {%4,%5,%6,%7}, {%8,%9}, {%0,%1,%2,%3};"
        : "+f"(d[0]), "+f"(d[1]), "+f"(d[2]), "+f"(d[3])
        : "r"(a[0]), "r"(a[1]), "r"(a[2]), "r"(a[3]), "r"(b0), "r"(b1));
}
__device__ __forceinline__ uint2 f4_to_h4(float4 v) {
    __half2 h0 = __floats2half2_rn(v.x, v.y);
    __half2 h1 = __floats2half2_rn(v.z, v.w);
    uint2 u;
    u.x = *reinterpret_cast<uint32_t*>(&h0);
    u.y = *reinterpret_cast<uint32_t*>(&h1);
    return u;
}

// ---- single kernel: CTA per s; resident fp16 X; W fp32->regs->fp16 ring,
//      STS deferred past the MMA block so LDG latency hides behind compute ----
__global__ __launch_bounds__(256, 2)
void pmha_fused2_kernel(const float* __restrict__ x,
                        const float* __restrict__ W,
                        const float* __restrict__ bias,
                        float* __restrict__ out)
{
    extern __shared__ char smem[];
    const uint32_t sb = smem_u32(smem);
    const uint32_t wbase = sb + XSMB;
    const int tid  = threadIdx.x;
    const int lane = tid & 31;
    const int wid  = tid >> 5;
    const int tg   = lane >> 2;
    const int tig  = lane & 3;
    const int wm   = (wid >> 2) * 64;
    const int wn   = (wid & 3) * 32;
    const int s    = blockIdx.x;
    const int widx = (s < 3) ? s : ((s & 1) ? 3 : 4);

    const float* xsrc = x + (size_t)s * HH;
    const float* Wf   = W + (size_t)widx * (HH * HH);

    // W staging map: 128 rows x 32 floats per k32 tile; 2 threads/row, 16 floats each
    const int srow  = tid >> 1;
    const int shalf = tid & 1;

    // ---- prologue: bias presum, issue W unit-0 LDGs, X conversion (hides them), STS unit 0 ----
    {
        float v = 0.0f;
        #pragma unroll
        for (int l = 0; l < 5; ++l) v += bias[l * HH + tid];
        *reinterpret_cast<float*>(smem + OBS + tid * 4) = v;
    }
    {
        const float* wr = Wf + (size_t)srow * HH + shalf * 16;
        float4 R0 = *reinterpret_cast<const float4*>(wr);
        float4 R1 = *reinterpret_cast<const float4*>(wr + 4);
        float4 R2 = *reinterpret_cast<const float4*>(wr + 8);
        float4 R3 = *reinterpret_cast<const float4*>(wr + 12);

        // X conversion: 128x256 fp32 -> resident fp16 (overlaps the W LDGs above)
        const int crow = tid >> 6;
        const int cc4  = tid & 63;
        #pragma unroll 8
        for (int p = 0; p < 32; ++p) {
            const int row = p * 4 + crow;
            float4 v = *reinterpret_cast<const float4*>(xsrc + (size_t)row * SSH + cc4 * 4);
            *reinterpret_cast<uint2*>(smem + (uint32_t)row * XROWB + (uint32_t)cc4 * 8) = f4_to_h4(v);
        }

        char* dst = smem + XSMB + (uint32_t)srow * WROWB + shalf * 32;  // slot 0
        *reinterpret_cast<uint2*>(dst +  0) = f4_to_h4(R0);
        *reinterpret_cast<uint2*>(dst +  8) = f4_to_h4(R1);
        *reinterpret_cast<uint2*>(dst + 16) = f4_to_h4(R2);
        *reinterpret_cast<uint2*>(dst + 24) = f4_to_h4(R3);
    }

    // ldmatrix base addresses
    const int lr = lane & 15;
    const int lc = lane >> 4;
    uint32_t aA[4], aB[2];
    #pragma unroll
    for (int i = 0; i < 4; ++i)
        aA[i] = sb + (uint32_t)(wm + i * 16 + lr) * XROWB + lc * 16;
    #pragma unroll
    for (int jj = 0; jj < 2; ++jj)
        aB[jj] = wbase + (uint32_t)(wn + jj * 16 + lr) * WROWB + lc * 16;

    float acc[4][4][4] = {};

    const float* bs = reinterpret_cast<const float*>(smem + OBS);
    auto epilogue = [&](int n0) {
        float bA[4], bB[4];
        #pragma unroll
        for (int j = 0; j < 4; ++j) {
            const int c = wn + j * 8 + 2 * tig;
            bA[j] = bs[n0 + c];
            bB[j] = bs[n0 + c + 1];
        }
        #pragma unroll
        for (int i = 0; i < 4; ++i) {
            const int r0 = wm + i * 16 + tg;
            float* o0 = out + (size_t)r0 * SSH + (size_t)s * HH + n0;
            float* o1 = o0 + (size_t)8 * SSH;
            #pragma unroll
            for (int j = 0; j < 4; ++j) {
                const int c = wn + j * 8 + 2 * tig;
                float2 v0 = make_float2(acc[i][j][0] + bA[j], acc[i][j][1] + bB[j]);
                float2 v1 = make_float2(acc[i][j][2] + bA[j], acc[i][j][3] + bB[j]);
                *reinterpret_cast<float2*>(o0 + c) = v0;
                *reinterpret_cast<float2*>(o1 + c) = v1;
            }
        }
    };

    #pragma unroll
    for (int u = 0; u < NUNIT; ++u) {
        __syncthreads();   // publishes slot u&1 (staged at end of prev iter / prologue)

        // 1) issue next unit's W LDGs (registers; no consumer until after the MMAs)
        float4 R0, R1, R2, R3;
        if (u + 1 < NUNIT) {
            const int nh = (u + 1) >> 3;
            const int k0 = ((u + 1) & 7) * 32;
            const float* wr = Wf + (size_t)(nh * 128 + srow) * HH + k0 + shalf * 16;
            R0 = *reinterpret_cast<const float4*>(wr);
            R1 = *reinterpret_cast<const float4*>(wr + 4);
            R2 = *reinterpret_cast<const float4*>(wr + 8);
            R3 = *reinterpret_cast<const float4*>(wr + 12);
        }

        // 2) compute unit u from slot u&1 (independent of the LDGs above)
        const uint32_t wst = (u & 1) * WTILEB;
        const uint32_t xkt = (uint32_t)(u & 7) * 64;   // 32 fp16 = 64B per k32 tile
        #pragma unroll
        for (int ks = 0; ks < 2; ++ks) {
            uint32_t a[4][4], b[2][4];
            #pragma unroll
            for (int i = 0; i < 4; ++i) ldsm_x4(a[i], aA[i] + xkt + ks * 32);
            #pragma unroll
            for (int jj = 0; jj < 2; ++jj) ldsm_x4(b[jj], aB[jj] + wst + ks * 32);
            #pragma unroll
            for (int i = 0; i < 4; ++i)
                #pragma unroll
                for (int j = 0; j < 4; ++j) {
                    const int jj = j >> 1, sel = j & 1;
                    mma_f16(acc[i][j], a[i], b[jj][sel], b[jj][sel + 2]);
                }
        }

        // 3) convert + store next unit's W into the other slot (LDG latency now absorbed)
        if (u + 1 < NUNIT) {
            char* dst = smem + XSMB + ((u + 1) & 1) * WTILEB + (uint32_t)srow * WROWB + shalf * 32;
            *reinterpret_cast<uint2*>(dst +  0) = f4_to_h4(R0);
            *reinterpret_cast<uint2*>(dst +  8) = f4_to_h4(R1);
            *reinterpret_cast<uint2*>(dst + 16) = f4_to_h4(R2);
            *reinterpret_cast<uint2*>(dst + 24) = f4_to_h4(R3);
        }

        if (u == 7) {      // n-half 0 done: write out, reset acc
            epilogue(0);
            #pragma unroll
            for (int i = 0; i < 4; ++i)
                #pragma unroll
                for (int j = 0; j < 4; ++j)
                    #pragma unroll
                    for (int q = 0; q < 4; ++q) acc[i][j][q] = 0.0f;
        }
    }
    epilogue(128);
}

extern "C" void kernel_launch(void* const* d_in, const int* in_sizes, int n_in,
                              void* d_out, int out_size)
{
    const float* x    = (const float*)d_in[0];   // [128, 513, 256]
    const float* W    = (const float*)d_in[1];   // [5, 256, 256]
    const float* bias = (const float*)d_in[2];   // [5, 256]
    float* out        = (float*)d_out;           // [128, 513, 4, 64]

    cudaFuncSetAttribute(pmha_fused2_kernel, cudaFuncAttributeMaxDynamicSharedMemorySize, SMTOT);
    pmha_fused2_kernel<<<SSEQ, 256, SMTOT>>>(x, W, bias, out);
}

// round 16
// speedup vs baseline: 1.4383x; 1.0638x over previous
#include <cuda_runtime.h>
#include <cuda_fp16.h>
#include <cstdint>

#define BB   128
#define SSEQ 513
#define HH   256
#define SSH  (SSEQ * HH)
#define SBH  (BB * HH)               // 32768: gx block per s

#define NX   (BB * SSEQ * HH)
#define NX8  (NX / 8)
#define NW   (5 * HH * HH)
#define NW8  (NW / 8)
#define NCVT (NX8 + NW8 + 32)

__device__ __half gx[NX];            // [s][b][h]  fp16 (contiguous 64KB block per s)
__device__ __half gw[NW];            // [widx][n][h] fp16
__device__ float  gbsum[HH];         // sum of 5 bias vectors

// ---------------- GEMM smem layout ----------------
#define XROWB 528                    // X resident: 128 rows x 256 fp16 (512B) + 16B pad
#define XSMB  (128 * XROWB)          // 67584
#define ROWB  144                    // W ring rows: 64 fp16 (128B) + 16B pad
#define WTILEB (128 * ROWB)          // 18432
#define SMTOT (XSMB + 2 * WTILEB)    // 104448
#define KT    64
#define NUNIT 8                      // 2 n-halves x 4 k-tiles

__device__ __forceinline__ uint32_t smem_u32(const void* p) {
    uint32_t a;
    asm("{ .reg .u64 t; cvta.to.shared.u64 t, %1; cvt.u32.u64 %0, t; }" : "=r"(a) : "l"(p));
    return a;
}
__device__ __forceinline__ void cpasync16(uint32_t dst, const void* src) {
    asm volatile("cp.async.ca.shared.global [%0], [%1], 16;" :: "r"(dst), "l"(src));
}
__device__ __forceinline__ void cp_commit() { asm volatile("cp.async.commit_group;"); }
__device__ __forceinline__ void cp_wait0()  { asm volatile("cp.async.wait_group 0;"); }
__device__ __forceinline__ void ldsm_x4(uint32_t* r, uint32_t addr) {
    asm volatile("ldmatrix.sync.aligned.m8n8.x4.shared.b16 {%0,%1,%2,%3}, [%4];"
                 : "=r"(r[0]), "=r"(r[1]), "=r"(r[2]), "=r"(r[3]) : "r"(addr));
}
__device__ __forceinline__ void mma_f16(float* d, const uint32_t* a, uint32_t b0, uint32_t b1) {
    asm volatile(
        "mma.sync.aligned.m16n8k16.row.col.f32.f16.f16.f32 "
        "{%0,%1,%2,%3}, {%4,%5,%6,%7}, {%8,%9}, {%0,%1,%2,%3};"
        : "+f"(d[0]), "+f"(d[1]), "+f"(d[2]), "+f"(d[3])
        : "r"(a[0]), "r"(a[1]), "r"(a[2]), "r"(a[3]), "r"(b0), "r"(b1));
}
__device__ __forceinline__ uint2 f4_to_h4(float4 v) {
    __half2 h0 = __floats2half2_rn(v.x, v.y);
    __half2 h1 = __floats2half2_rn(v.z, v.w);
    uint2 u;
    u.x = *reinterpret_cast<uint32_t*>(&h0);
    u.y = *reinterpret_cast<uint32_t*>(&h1);
    return u;
}

// ---- kernel 1: fp32 -> fp16, x transposed to [s][b][h], W straight, bias presum ----
__global__ __launch_bounds__(256)
void cvt_kernel(const float* __restrict__ x,
                const float* __restrict__ W,
                const float* __restrict__ bias)
{
    const uint32_t id = blockIdx.x * 256 + threadIdx.x;
    if (id < NX8) {
        const size_t f = (size_t)id * 8;
        const int b   = (int)(f / (SSEQ * HH));
        const int rem = (int)(f % (SSEQ * HH));
        const int s   = rem / HH;
        const int h   = rem % HH;
        float4 v0 = *reinterpret_cast<const float4*>(x + f);
        float4 v1 = *reinterpret_cast<const float4*>(x + f + 4);
        uint2 a = f4_to_h4(v0), c = f4_to_h4(v1);
        *reinterpret_cast<uint4*>(&gx[(size_t)s * SBH + (size_t)b * HH + h]) =
            make_uint4(a.x, a.y, c.x, c.y);
    } else if (id < NX8 + NW8) {
        const size_t f = (size_t)(id - NX8) * 8;
        float4 v0 = *reinterpret_cast<const float4*>(W + f);
        float4 v1 = *reinterpret_cast<const float4*>(W + f + 4);
        uint2 a = f4_to_h4(v0), c = f4_to_h4(v1);
        *reinterpret_cast<uint4*>(&gw[f]) = make_uint4(a.x, a.y, c.x, c.y);
    } else if (id < NCVT) {
        const int t = (int)(id - NX8 - NW8);
        #pragma unroll
        for (int j = 0; j < 8; ++j) {
            const int c = t * 8 + j;
            float v = 0.0f;
            #pragma unroll
            for (int l = 0; l < 5; ++l) v += bias[l * HH + c];
            gbsum[c] = v;
        }
    }
}

// ---- kernel 2: resident-X fp16 GEMM. One CTA per s, full N=256. ----
// out[0:128, s, 0:256] = x_s @ W[idx]^T + bsum
__global__ __launch_bounds__(256, 2)
void pmha_resx_kernel(float* __restrict__ out)
{
    extern __shared__ char smem[];
    const uint32_t sb = smem_u32(smem);
    const uint32_t wbase = sb + XSMB;
    const int tid  = threadIdx.x;
    const int lane = tid & 31;
    const int wid  = tid >> 5;
    const int tg   = lane >> 2;
    const int tig  = lane & 3;
    const int wm   = (wid >> 2) * 64;
    const int wn   = (wid & 3) * 32;
    const int s    = blockIdx.x;
    const int widx = (s < 3) ? s : ((s & 1) ? 3 : 4);

    const __half* xs = gx + (size_t)s * SBH;        // 128x256 fp16, fully contiguous
    const __half* Wb = gw + (size_t)widx * (HH * HH);

    // W ring prefetch: unit u -> slot u&1; nh = u>>2, k0 = (u&3)*64
    const int prow = tid >> 3;       // 0..31 (x4 steps of 32)
    const int pc   = tid & 7;        // 16B chunk 0..7
    auto prefetchW = [&](int u) {
        const __half* Wp = Wb + (size_t)((u >> 2) * 128) * HH + (u & 3) * KT;
        const uint32_t base = wbase + (u & 1) * WTILEB;
        #pragma unroll
        for (int t = 0; t < 4; ++t) {
            const int row = prow + t * 32;
            cpasync16(base + (uint32_t)row * ROWB + (uint32_t)pc * 16,
                      Wp + (size_t)row * HH + pc * 8);
        }
    };

    // prologue: whole X block (4096 16B chunks; 16 per thread) + W unit 0, one group
    {
        const int xrow = tid >> 5;   // 0..7 (x16 steps of 8)
        const int xc   = tid & 31;   // 16B chunk within row, 0..31
        #pragma unroll
        for (int t = 0; t < 16; ++t) {
            const int row = xrow + t * 8;
            cpasync16(sb + (uint32_t)row * XROWB + (uint32_t)xc * 16,
                      xs + (size_t)row * HH + xc * 8);
        }
    }
    prefetchW(0);
    cp_commit();

    // ldmatrix base addresses
    const int lr = lane & 15;
    const int lc = lane >> 4;
    uint32_t aA[4], aB[2];
    #pragma unroll
    for (int i = 0; i < 4; ++i)
        aA[i] = sb + (uint32_t)(wm + i * 16 + lr) * XROWB + lc * 16;
    #pragma unroll
    for (int jj = 0; jj < 2; ++jj)
        aB[jj] = wbase + (uint32_t)(wn + jj * 16 + lr) * ROWB + lc * 16;

    float acc[4][4][4] = {};

    auto epilogue = [&](int n0) {
        float bA[4], bB[4];
        #pragma unroll
        for (int j = 0; j < 4; ++j) {
            const int c = wn + j * 8 + 2 * tig;
            bA[j] = gbsum[n0 + c];
            bB[j] = gbsum[n0 + c + 1];
        }
        #pragma unroll
        for (int i = 0; i < 4; ++i) {
            const int r0 = wm + i * 16 + tg;
            float* o0 = out + (size_t)r0 * SSH + (size_t)s * HH + n0;
            float* o1 = o0 + (size_t)8 * SSH;
            #pragma unroll
            for (int j = 0; j < 4; ++j) {
                const int c = wn + j * 8 + 2 * tig;
                float2 v0 = make_float2(acc[i][j][0] + bA[j], acc[i][j][1] + bB[j]);
                float2 v1 = make_float2(acc[i][j][2] + bA[j], acc[i][j][3] + bB[j]);
                *reinterpret_cast<float2*>(o0 + c) = v0;
                *reinterpret_cast<float2*>(o1 + c) = v1;
            }
        }
    };

    #pragma unroll
    for (int u = 0; u < NUNIT; ++u) {
        cp_wait0();          // unit u's W tile (and, at u=0, the whole X block) arrived
        __syncthreads();     // also retires readers of the slot we are about to refill

        if (u + 1 < NUNIT) { prefetchW(u + 1); cp_commit(); }

        const uint32_t wst = (u & 1) * WTILEB;
        const uint32_t xkt = (uint32_t)(u & 3) * 128;   // 64 fp16 = 128B per k-tile
        #pragma unroll
        for (int ks = 0; ks < 4; ++ks) {
            uint32_t a[4][4], b[2][4];
            #pragma unroll
            for (int i = 0; i < 4; ++i) ldsm_x4(a[i], aA[i] + xkt + ks * 32);
            #pragma unroll
            for (int jj = 0; jj < 2; ++jj) ldsm_x4(b[jj], aB[jj] + wst + ks * 32);
            #pragma unroll
            for (int i = 0; i < 4; ++i)
                #pragma unroll
                for (int j = 0; j < 4; ++j) {
                    const int jj = j >> 1, sel = j & 1;
                    mma_f16(acc[i][j], a[i], b[jj][sel], b[jj][sel + 2]);
                }
        }

        if (u == 3) {        // n-half 0 complete
            epilogue(0);
            #pragma unroll
            for (int i = 0; i < 4; ++i)
                #pragma unroll
                for (int j = 0; j < 4; ++j)
                    #pragma unroll
                    for (int q = 0; q < 4; ++q) acc[i][j][q] = 0.0f;
        }
    }
    epilogue(128);
}

extern "C" void kernel_launch(void* const* d_in, const int* in_sizes, int n_in,
                              void* d_out, int out_size)
{
    const float* x    = (const float*)d_in[0];   // [128, 513, 256]
    const float* W    = (const float*)d_in[1];   // [5, 256, 256]
    const float* bias = (const float*)d_in[2];   // [5, 256]
    float* out        = (float*)d_out;           // [128, 513, 4, 64]

    cvt_kernel<<<(NCVT + 255) / 256, 256>>>(x, W, bias);

    cudaFuncSetAttribute(pmha_resx_kernel, cudaFuncAttributeMaxDynamicSharedMemorySize, SMTOT);
    pmha_resx_kernel<<<SSEQ, 256, SMTOT>>>(out);
}